// round 16
// baseline (speedup 1.0000x reference)
#include <cuda_runtime.h>
#include <cuda_bf16.h>
#include <math.h>
#include <stdint.h>

#define Bb 4
#define Tt 64
#define Cc 256
#define Ff 256
#define Hh 8
#define Dd 32
#define HIDN 512
#define BT (Bb*Tt)            // 256
#define ROWS (BT*Ff)          // 65536
#define C3 (3*Cc)             // 768

// ---------------- scratch (device globals; resolved via cudaGetSymbolAddress) ----
__device__ float          g_xs  [ROWS*Cc];    // residual fp32 (raw transposed x)
__device__ float          g_out1[ROWS*Cc];    // after proj + residual
__device__ __nv_bfloat16  g_xn  [ROWS*Cc];    // LN out (bf16)
__device__ __nv_bfloat16  g_att [ROWS*Cc];    // attention out (bf16)
__device__ __nv_bfloat16  g_qkv [ROWS*C3];    // qkv bf16; reused as MLP hidden
__device__ __nv_bfloat16  g_wqkvT [C3*Cc];    // transposed bf16 weights [N][K]
__device__ __nv_bfloat16  g_wprojT[Cc*Cc];
__device__ __nv_bfloat16  g_w1T   [HIDN*Cc];
__device__ __nv_bfloat16  g_w2T   [Cc*HIDN];

__device__ __forceinline__ uint32_t smem_u32(const void* p) {
    uint32_t a;
    asm("{ .reg .u64 t; cvta.to.shared.u64 t, %1; cvt.u32.u64 %0, t; }" : "=r"(a) : "l"(p));
    return a;
}
__device__ __forceinline__ void ldsm4(uint32_t& r0, uint32_t& r1, uint32_t& r2, uint32_t& r3,
                                      uint32_t addr) {
    asm volatile("ldmatrix.sync.aligned.m8n8.x4.shared.b16 {%0,%1,%2,%3}, [%4];"
                 : "=r"(r0), "=r"(r1), "=r"(r2), "=r"(r3) : "r"(addr));
}
__device__ __forceinline__ void ldsm4t(uint32_t& r0, uint32_t& r1, uint32_t& r2, uint32_t& r3,
                                       uint32_t addr) {
    asm volatile("ldmatrix.sync.aligned.m8n8.x4.trans.shared.b16 {%0,%1,%2,%3}, [%4];"
                 : "=r"(r0), "=r"(r1), "=r"(r2), "=r"(r3) : "r"(addr));
}
__device__ __forceinline__ void mma16816(float* c, const uint32_t* a, const uint32_t* b) {
    asm volatile(
        "mma.sync.aligned.m16n8k16.row.col.f32.bf16.bf16.f32 "
        "{%0,%1,%2,%3}, {%4,%5,%6,%7}, {%8,%9}, {%0,%1,%2,%3};"
        : "+f"(c[0]), "+f"(c[1]), "+f"(c[2]), "+f"(c[3])
        : "r"(a[0]), "r"(a[1]), "r"(a[2]), "r"(a[3]), "r"(b[0]), "r"(b[1]));
}
__device__ __forceinline__ void cp16(uint32_t sdst, const void* gsrc) {
    asm volatile("cp.async.cg.shared.global [%0], [%1], 16;" :: "r"(sdst), "l"(gsrc));
}
__device__ __forceinline__ uint32_t ex2_bf16x2(uint32_t a) {
    uint32_t d;
    asm("ex2.approx.ftz.bf16x2 %0, %1;" : "=r"(d) : "r"(a));
    return d;
}
#define CP_COMMIT() asm volatile("cp.async.commit_group;" ::: "memory")
#define CP_WAIT(n)  asm volatile("cp.async.wait_group %0;" :: "n"(n) : "memory")

// ================= fused input: transpose x(b,c,t,f)->(bt,f,c) + LN1 =================
__global__ __launch_bounds__(256)
void k_in(const float* __restrict__ x, float* __restrict__ xs,
          __nv_bfloat16* __restrict__ xn,
          const float* __restrict__ g, const float* __restrict__ be) {
    __shared__ float tile[256][33];
    __shared__ float ps_[8][32], pq_[8][32];
    __shared__ float smu[32], srs[32];
    int bt = blockIdx.y, f0 = blockIdx.x * 32;
    int b = bt >> 6, t = bt & 63;
    int tid = threadIdx.x;
    int f = tid & 31, s = tid >> 5;

    const float* xb = x + ((size_t)b*Cc*Tt + t)*Ff + f0;
    float sm = 0.f, sq = 0.f;
    #pragma unroll 8
    for (int i = 0; i < 32; i++) {
        int c = s + i*8;
        float v = xb[(size_t)c*Tt*Ff + f];
        tile[c][f] = v;
        sm += v; sq += v*v;
    }
    ps_[s][f] = sm; pq_[s][f] = sq;
    __syncthreads();
    if (tid < 32) {
        float S = 0.f, Q = 0.f;
        #pragma unroll
        for (int k = 0; k < 8; k++) { S += ps_[k][tid]; Q += pq_[k][tid]; }
        float mu = S * (1.0f/Cc);
        float var = Q * (1.0f/Cc) - mu*mu;
        smu[tid] = mu;
        srs[tid] = rsqrtf(var + 1e-5f);
    }
    __syncthreads();
    float gc = g[tid], bc = be[tid];
    #pragma unroll 8
    for (int i = 0; i < 32; i++) {
        float v = tile[tid][i];
        size_t o = ((size_t)bt*Ff + f0 + i)*Cc + tid;
        xs[o] = v;
        xn[o] = __float2bfloat16((v - smu[i]) * srs[i] * gc + bc);
    }
}

// ================= layernorm (256) -> bf16 =================
__global__ void k_ln(const float* __restrict__ in, __nv_bfloat16* __restrict__ outn,
                     const float* __restrict__ g, const float* __restrict__ be) {
    int row = blockIdx.x;
    int tid = threadIdx.x;
    float v = in[(size_t)row*Cc + tid];
    float s = v, q = v*v;
    #pragma unroll
    for (int o = 16; o; o >>= 1) {
        s += __shfl_xor_sync(0xffffffffu, s, o);
        q += __shfl_xor_sync(0xffffffffu, q, o);
    }
    __shared__ float ws[8], wq[8], mv[2];
    int w = tid >> 5, l = tid & 31;
    if (l == 0) { ws[w] = s; wq[w] = q; }
    __syncthreads();
    if (tid == 0) {
        float S = 0.f, Q = 0.f;
        #pragma unroll
        for (int i = 0; i < 8; i++) { S += ws[i]; Q += wq[i]; }
        float mu = S * (1.0f/Cc);
        float var = Q * (1.0f/Cc) - mu*mu;
        mv[0] = mu;
        mv[1] = rsqrtf(var + 1e-5f);
    }
    __syncthreads();
    outn[(size_t)row*Cc + tid] = __float2bfloat16((v - mv[0]) * mv[1] * g[tid] + be[tid]);
}

// ================= all weight transposes in one kernel =================
__global__ void k_wtall(const float* __restrict__ Wqkv, const float* __restrict__ Wproj,
                        const float* __restrict__ W1, const float* __restrict__ W2,
                        __nv_bfloat16* __restrict__ wqkvT, __nv_bfloat16* __restrict__ wprojT,
                        __nv_bfloat16* __restrict__ w1T, __nv_bfloat16* __restrict__ w2T) {
    int idx = blockIdx.x * 256 + threadIdx.x;
    if (idx < C3*Cc) {
        int n = idx / Cc, k = idx - n*Cc;
        wqkvT[idx] = __float2bfloat16(Wqkv[(size_t)k*C3 + n]);
    } else if (idx < C3*Cc + Cc*Cc) {
        int j = idx - C3*Cc;
        int n = j / Cc, k = j - n*Cc;
        wprojT[j] = __float2bfloat16(Wproj[(size_t)k*Cc + n]);
    } else if (idx < C3*Cc + Cc*Cc + HIDN*Cc) {
        int j = idx - C3*Cc - Cc*Cc;
        int n = j / Cc, k = j - n*Cc;
        w1T[j] = __float2bfloat16(W1[(size_t)k*HIDN + n]);
    } else if (idx < C3*Cc + Cc*Cc + HIDN*Cc + Cc*HIDN) {
        int j = idx - C3*Cc - Cc*Cc - HIDN*Cc;
        int n = j / HIDN, k = j - n*HIDN;
        w2T[j] = __float2bfloat16(W2[(size_t)k*Cc + n]);
    }
}

// ================= HMMA bf16 GEMM: C = A(M,K) @ Bt(N,K)^T =================
// CTA tile 256x128, 8 warps = 4(M) x 2(N) of 64x64. 32 mma per 8 ldsm.
// 3-stage cp.async ring: stage = A(32KB) + B(16KB) = 48KB, total 144KB, 1 CTA/SM.
#define GEMM_SMEM (3*49152)   // 147456 B
template<int OUT_MODE, int HAS_BIAS, int GELU_F, int HAS_RES>
__global__ __launch_bounds__(256)
void k_mmagemm(const __nv_bfloat16* __restrict__ A, const __nv_bfloat16* __restrict__ Bt,
               void* __restrict__ Co, const float* __restrict__ bias,
               const float* __restrict__ res, int N, int K) {
    extern __shared__ __nv_bfloat16 smg[];
    int tid = threadIdx.x, wid = tid >> 5, lid = tid & 31;
    int m0 = blockIdx.y * 256, n0 = blockIdx.x * 128;
    int wm = (wid & 3) * 64;        // 4 M warps
    int wn = (wid >> 2) * 64;       // 2 N warps

    int lrow = tid >> 3, lkb = tid & 7;
    uint32_t swoff = (lkb ^ (lrow & 7)) * 8;

    float c[4][8][4];
    #pragma unroll
    for (int mi = 0; mi < 4; mi++)
        #pragma unroll
        for (int ni = 0; ni < 8; ni++)
            #pragma unroll
            for (int j = 0; j < 4; j++) c[mi][ni][j] = 0.f;

    uint32_t sBase = smem_u32(smg);
    int nch = K >> 6;

    auto load_chunk = [&](int ck) {
        int k0 = ck << 6;
        uint32_t st = sBase + (ck % 3) * 49152;
        const __nv_bfloat16* ga = A  + (size_t)(m0 + lrow)*K + k0 + lkb*8;
        const __nv_bfloat16* gb = Bt + (size_t)(n0 + lrow)*K + k0 + lkb*8;
        #pragma unroll
        for (int i = 0; i < 8; i++) {       // A: 256 rows
            uint32_t d = ((lrow + i*32)*64 + swoff) * 2;
            cp16(st + d, ga + (size_t)(i*32)*K);
        }
        #pragma unroll
        for (int i = 0; i < 4; i++) {       // B: 128 rows
            uint32_t d = ((lrow + i*32)*64 + swoff) * 2;
            cp16(st + 32768 + d, gb + (size_t)(i*32)*K);
        }
        CP_COMMIT();
    };

    load_chunk(0);
    if (nch > 1) load_chunk(1);

    for (int cck = 0; cck < nch; cck++) {
        if (cck + 1 < nch) { CP_WAIT(1); } else { CP_WAIT(0); }
        __syncthreads();
        if (cck + 2 < nch) load_chunk(cck + 2);

        uint32_t sA = sBase + (cck % 3) * 49152;
        uint32_t sB = sA + 32768;
        #pragma unroll
        for (int ks = 0; ks < 4; ks++) {
            uint32_t a[4][4], b[8][2];
            #pragma unroll
            for (int mi = 0; mi < 4; mi++) {
                int row = wm + mi*16 + (lid & 15);
                int kb  = ks*2 + (lid >> 4);
                uint32_t ad = sA + (row*64 + ((kb ^ (row & 7))*8))*2;
                ldsm4(a[mi][0], a[mi][1], a[mi][2], a[mi][3], ad);
            }
            #pragma unroll
            for (int nh = 0; nh < 4; nh++) {
                int nrow = wn + nh*16 + (lid & 7) + ((lid >> 4) << 3);
                int kb   = ks*2 + ((lid >> 3) & 1);
                uint32_t bd = sB + (nrow*64 + ((kb ^ (nrow & 7))*8))*2;
                uint32_t r0, r1, r2, r3;
                ldsm4(r0, r1, r2, r3, bd);
                b[nh*2+0][0] = r0; b[nh*2+0][1] = r1;
                b[nh*2+1][0] = r2; b[nh*2+1][1] = r3;
            }
            #pragma unroll
            for (int mi = 0; mi < 4; mi++)
                #pragma unroll
                for (int ni = 0; ni < 8; ni++)
                    mma16816(c[mi][ni], a[mi], b[ni]);
        }
        __syncthreads();
    }

    int qr = lid >> 2, qc = (lid & 3) * 2;
    #pragma unroll
    for (int mi = 0; mi < 4; mi++) {
        #pragma unroll
        for (int half = 0; half < 2; half++) {
            int m = m0 + wm + mi*16 + qr + half*8;
            #pragma unroll
            for (int ni = 0; ni < 8; ni++) {
                int n = n0 + wn + ni*8 + qc;
                float v0 = c[mi][ni][half*2+0];
                float v1 = c[mi][ni][half*2+1];
                if (HAS_BIAS) { v0 += bias[n]; v1 += bias[n+1]; }
                if (GELU_F) {
                    v0 = 0.5f*v0*(1.0f + erff(v0*0.7071067811865475f));
                    v1 = 0.5f*v1*(1.0f + erff(v1*0.7071067811865475f));
                }
                if (HAS_RES) {
                    float2 r2 = *(const float2*)&res[(size_t)m*N + n];
                    v0 += r2.x; v1 += r2.y;
                }
                if (OUT_MODE == 1) {
                    *(__nv_bfloat162*)((__nv_bfloat16*)Co + (size_t)m*N + n) =
                        __floats2bfloat162_rn(v0, v1);
                } else if (OUT_MODE == 0) {
                    *(float2*)((float*)Co + (size_t)m*N + n) = make_float2(v0, v1);
                } else {
                    int bt2 = m >> 8, fF = m & 255;
                    int b2 = bt2 >> 6, t2 = bt2 & 63;
                    float* op = (float*)Co + ((size_t)(b2*Cc + n)*Tt + t2)*Ff + fF;
                    op[0] = v0;
                    op[(size_t)Tt*Ff] = v1;
                }
            }
        }
    }
}

// ================= attention via HMMA (conv3 fused), block per (bt,h) =================
// (round-15 state, frozen)
#define ATTN_SMEM (3*256*40*2)   // 61440 B

__global__ __launch_bounds__(256, 2)
void k_attn(const __nv_bfloat16* __restrict__ qkvg, const float* __restrict__ dww,
            const float* __restrict__ temp, __nv_bfloat16* __restrict__ attn_out) {
    extern __shared__ __nv_bfloat16 smA[];
    __nv_bfloat16* Qs = smA;
    __nv_bfloat16* Ks = smA + 256*40;
    __nv_bfloat16* Vs = smA + 2*256*40;
    __shared__ float wsm[3*32*3];

    int bt = blockIdx.x, h = blockIdx.y;
    int tid = threadIdx.x, w = tid >> 5, l = tid & 31;
    const __nv_bfloat16* qkvb = qkvg + (size_t)bt*Ff*C3;
    float tpl = temp[h] * 1.44269504f;

    if (tid < 96) {
        int t = tid >> 5, d = tid & 31;
        int ch = t*Cc + h*Dd + d;
        wsm[tid*3+0] = dww[ch*3+0];
        wsm[tid*3+1] = dww[ch*3+1];
        wsm[tid*3+2] = dww[ch*3+2];
    }
    __syncthreads();

    {
        int j = tid;
        bool hasm = (j > 0), hasp = (j < Ff-1);
        const __nv_bfloat16* base = qkvb + (size_t)j*C3 + h*Dd;
        float acc[32];
        const uint4 z4 = make_uint4(0u, 0u, 0u, 0u);

        auto conv_one = [&](int off, const float* wt) {
            uint4 rm[4], rc[4], rp[4];
            const uint4* pc = (const uint4*)(base + off);
            const uint4* pm = (const uint4*)(base + off - C3);
            const uint4* pp = (const uint4*)(base + off + C3);
            #pragma unroll
            for (int i = 0; i < 4; i++) {
                rc[i] = pc[i];
                rm[i] = hasm ? pm[i] : z4;
                rp[i] = hasp ? pp[i] : z4;
            }
            const __nv_bfloat162* m2 = (const __nv_bfloat162*)rm;
            const __nv_bfloat162* c2 = (const __nv_bfloat162*)rc;
            const __nv_bfloat162* p2 = (const __nv_bfloat162*)rp;
            #pragma unroll
            for (int d = 0; d < 16; d++) {
                float2 cv = __bfloat1622float2(c2[d]);
                float2 mv = __bfloat1622float2(m2[d]);
                float2 pv = __bfloat1622float2(p2[d]);
                acc[2*d]   = wt[(2*d)*3+0]*mv.x + wt[(2*d)*3+1]*cv.x + wt[(2*d)*3+2]*pv.x;
                acc[2*d+1] = wt[(2*d+1)*3+0]*mv.y + wt[(2*d+1)*3+1]*cv.y + wt[(2*d+1)*3+2]*pv.y;
            }
        };
        auto store_s = [&](__nv_bfloat16* T, float sc) {
            uint4 pk4[4];
            uint32_t* pk = (uint32_t*)pk4;
            #pragma unroll
            for (int d = 0; d < 16; d++) {
                __nv_bfloat162 hh = __floats2bfloat162_rn(acc[2*d]*sc, acc[2*d+1]*sc);
                pk[d] = *(uint32_t*)&hh;
            }
            uint4* dst = (uint4*)(T + (size_t)j*40);
            #pragma unroll
            for (int i = 0; i < 4; i++) dst[i] = pk4[i];
        };

        conv_one(0, wsm);
        float ss = 0.f;
        #pragma unroll
        for (int d = 0; d < 32; d++) ss += acc[d]*acc[d];
        store_s(Qs, 1.f / fmaxf(sqrtf(ss), 1e-12f));

        conv_one(Cc, wsm + 96);
        ss = 0.f;
        #pragma unroll
        for (int d = 0; d < 32; d++) ss += acc[d]*acc[d];
        store_s(Ks, 1.f / fmaxf(sqrtf(ss), 1e-12f));

        conv_one(2*Cc, wsm + 192);
        store_s(Vs, 1.f);
    }
    __syncthreads();

    uint32_t sQ = smem_u32(Qs), sK = smem_u32(Ks), sV = smem_u32(Vs);
    int lid = l;
    int qr = lid >> 2;
    int m0a = w*32, m0b = w*32 + 16;

    uint32_t aA[2][4], aB[2][4];
    #pragma unroll
    for (int ks = 0; ks < 2; ks++) {
        int kb = ks*2 + (lid >> 4);
        ldsm4(aA[ks][0], aA[ks][1], aA[ks][2], aA[ks][3],
              sQ + ((m0a + (lid & 15))*40 + kb*8)*2);
        ldsm4(aB[ks][0], aB[ks][1], aB[ks][2], aB[ks][3],
              sQ + ((m0b + (lid & 15))*40 + kb*8)*2);
    }

    float ovA[4][4], ovB[4][4];
    #pragma unroll
    for (int nt = 0; nt < 4; nt++)
        #pragma unroll
        for (int j = 0; j < 4; j++) { ovA[nt][j] = 0.f; ovB[nt][j] = 0.f; }
    float zAlo = 0.f, zAhi = 0.f, zBlo = 0.f, zBhi = 0.f;

    for (int ch = 0; ch < 8; ch++) {
        float sA_[4][4], sB_[4][4];
        #pragma unroll
        for (int nt = 0; nt < 4; nt++)
            #pragma unroll
            for (int j = 0; j < 4; j++) { sA_[nt][j] = 0.f; sB_[nt][j] = 0.f; }
        #pragma unroll
        for (int g = 0; g < 2; g++) {
            #pragma unroll
            for (int ks = 0; ks < 2; ks++) {
                int nrow = ch*32 + g*16 + (lid & 7) + ((lid >> 4) << 3);
                int kb   = ks*2 + ((lid >> 3) & 1);
                uint32_t r0, r1, r2, r3;
                ldsm4(r0, r1, r2, r3, sK + (nrow*40 + kb*8)*2);
                uint32_t b0[2] = {r0, r1}, b1[2] = {r2, r3};
                mma16816(sA_[g*2],   aA[ks], b0);
                mma16816(sA_[g*2+1], aA[ks], b1);
                mma16816(sB_[g*2],   aB[ks], b0);
                mma16816(sB_[g*2+1], aB[ks], b1);
            }
        }
        #pragma unroll
        for (int kk = 0; kk < 2; kk++) {
            uint32_t paA[4], paB[4];
            {
                __nv_bfloat162 t0 = __floats2bfloat162_rn(sA_[2*kk][0]*tpl,   sA_[2*kk][1]*tpl);
                __nv_bfloat162 t1 = __floats2bfloat162_rn(sA_[2*kk][2]*tpl,   sA_[2*kk][3]*tpl);
                __nv_bfloat162 t2 = __floats2bfloat162_rn(sA_[2*kk+1][0]*tpl, sA_[2*kk+1][1]*tpl);
                __nv_bfloat162 t3 = __floats2bfloat162_rn(sA_[2*kk+1][2]*tpl, sA_[2*kk+1][3]*tpl);
                paA[0] = ex2_bf16x2(*(uint32_t*)&t0);
                paA[1] = ex2_bf16x2(*(uint32_t*)&t1);
                paA[2] = ex2_bf16x2(*(uint32_t*)&t2);
                paA[3] = ex2_bf16x2(*(uint32_t*)&t3);
                __nv_bfloat162 u0 = __floats2bfloat162_rn(sB_[2*kk][0]*tpl,   sB_[2*kk][1]*tpl);
                __nv_bfloat162 u1 = __floats2bfloat162_rn(sB_[2*kk][2]*tpl,   sB_[2*kk][3]*tpl);
                __nv_bfloat162 u2 = __floats2bfloat162_rn(sB_[2*kk+1][0]*tpl, sB_[2*kk+1][1]*tpl);
                __nv_bfloat162 u3 = __floats2bfloat162_rn(sB_[2*kk+1][2]*tpl, sB_[2*kk+1][3]*tpl);
                paB[0] = ex2_bf16x2(*(uint32_t*)&u0);
                paB[1] = ex2_bf16x2(*(uint32_t*)&u1);
                paB[2] = ex2_bf16x2(*(uint32_t*)&u2);
                paB[3] = ex2_bf16x2(*(uint32_t*)&u3);
            }
            {
                float2 p0 = __bfloat1622float2(*(__nv_bfloat162*)&paA[0]);
                float2 p1 = __bfloat1622float2(*(__nv_bfloat162*)&paA[1]);
                float2 p2 = __bfloat1622float2(*(__nv_bfloat162*)&paA[2]);
                float2 p3 = __bfloat1622float2(*(__nv_bfloat162*)&paA[3]);
                zAlo += p0.x + p0.y + p2.x + p2.y;
                zAhi += p1.x + p1.y + p3.x + p3.y;
                float2 q0 = __bfloat1622float2(*(__nv_bfloat162*)&paB[0]);
                float2 q1 = __bfloat1622float2(*(__nv_bfloat162*)&paB[1]);
                float2 q2 = __bfloat1622float2(*(__nv_bfloat162*)&paB[2]);
                float2 q3 = __bfloat1622float2(*(__nv_bfloat162*)&paB[3]);
                zBlo += q0.x + q0.y + q2.x + q2.y;
                zBhi += q1.x + q1.y + q3.x + q3.y;
            }
            int vrow = ch*32 + kk*16 + (lid & 15);
            #pragma unroll
            for (int half = 0; half < 2; half++) {
                uint32_t r0, r1, r2, r3;
                ldsm4t(r0, r1, r2, r3, sV + (vrow*40)*2 + (lid >> 4)*16 + half*32);
                uint32_t b0[2] = {r0, r1}, b1[2] = {r2, r3};
                mma16816(ovA[half*2+0], paA, b0);
                mma16816(ovA[half*2+1], paA, b1);
                mma16816(ovB[half*2+0], paB, b0);
                mma16816(ovB[half*2+1], paB, b1);
            }
        }
    }

    #pragma unroll
    for (int o = 1; o <= 2; o <<= 1) {
        zAlo += __shfl_xor_sync(0xffffffffu, zAlo, o);
        zAhi += __shfl_xor_sync(0xffffffffu, zAhi, o);
        zBlo += __shfl_xor_sync(0xffffffffu, zBlo, o);
        zBhi += __shfl_xor_sync(0xffffffffu, zBhi, o);
    }
    float iAlo = 1.f/zAlo, iAhi = 1.f/zAhi;
    float iBlo = 1.f/zBlo, iBhi = 1.f/zBhi;
    #pragma unroll
    for (int nt = 0; nt < 4; nt++) {
        int col = h*Dd + nt*8 + (lid & 3)*2;
        *(__nv_bfloat162*)&attn_out[((size_t)bt*Ff + m0a + qr    )*Cc + col] =
            __floats2bfloat162_rn(ovA[nt][0]*iAlo, ovA[nt][1]*iAlo);
        *(__nv_bfloat162*)&attn_out[((size_t)bt*Ff + m0a + qr + 8)*Cc + col] =
            __floats2bfloat162_rn(ovA[nt][2]*iAhi, ovA[nt][3]*iAhi);
        *(__nv_bfloat162*)&attn_out[((size_t)bt*Ff + m0b + qr    )*Cc + col] =
            __floats2bfloat162_rn(ovB[nt][0]*iBlo, ovB[nt][1]*iBlo);
        *(__nv_bfloat162*)&attn_out[((size_t)bt*Ff + m0b + qr + 8)*Cc + col] =
            __floats2bfloat162_rn(ovB[nt][2]*iBhi, ovB[nt][3]*iBhi);
    }
}

// ================= launch =================
extern "C" void kernel_launch(void* const* d_in, const int* in_sizes, int n_in,
                              void* d_out, int out_size) {
    const float *x, *n1g, *n1b, *Wqkv, *dww, *Wproj, *temp, *n2g, *n2b, *W1, *b1, *W2, *b2;
    const int X_SIZE = Bb*Cc*Tt*Ff;
    if (n_in >= 13 && in_sizes[0] == X_SIZE) {
        x     = (const float*)d_in[0];  n1g   = (const float*)d_in[1];
        n1b   = (const float*)d_in[2];  Wqkv  = (const float*)d_in[3];
        dww   = (const float*)d_in[4];  Wproj = (const float*)d_in[5];
        temp  = (const float*)d_in[6];  n2g   = (const float*)d_in[7];
        n2b   = (const float*)d_in[8];  W1    = (const float*)d_in[9];
        b1    = (const float*)d_in[10]; W2    = (const float*)d_in[11];
        b2    = (const float*)d_in[12];
    } else {
        W1    = (const float*)d_in[0];  W2    = (const float*)d_in[1];
        Wproj = (const float*)d_in[2];  Wqkv  = (const float*)d_in[3];
        b1    = (const float*)d_in[4];  b2    = (const float*)d_in[5];
        dww   = (const float*)d_in[6];  n1b   = (const float*)d_in[7];
        n1g   = (const float*)d_in[8];  n2b   = (const float*)d_in[9];
        n2g   = (const float*)d_in[10]; temp  = (const float*)d_in[11];
        x     = (const float*)d_in[12];
    }

    void *vp;
    float *xs, *out1;
    __nv_bfloat16 *xn, *att, *qkv, *wqkvT, *wprojT, *w1T, *w2T;
    cudaGetSymbolAddress(&vp, g_xs);     xs     = (float*)vp;
    cudaGetSymbolAddress(&vp, g_out1);   out1   = (float*)vp;
    cudaGetSymbolAddress(&vp, g_xn);     xn     = (__nv_bfloat16*)vp;
    cudaGetSymbolAddress(&vp, g_att);    att    = (__nv_bfloat16*)vp;
    cudaGetSymbolAddress(&vp, g_qkv);    qkv    = (__nv_bfloat16*)vp;
    cudaGetSymbolAddress(&vp, g_wqkvT);  wqkvT  = (__nv_bfloat16*)vp;
    cudaGetSymbolAddress(&vp, g_wprojT); wprojT = (__nv_bfloat16*)vp;
    cudaGetSymbolAddress(&vp, g_w1T);    w1T    = (__nv_bfloat16*)vp;
    cudaGetSymbolAddress(&vp, g_w2T);    w2T    = (__nv_bfloat16*)vp;
    __nv_bfloat16* hid = qkv;

    cudaFuncSetAttribute(k_attn, cudaFuncAttributeMaxDynamicSharedMemorySize, ATTN_SMEM);
    cudaFuncSetAttribute(k_mmagemm<1,0,0,0>, cudaFuncAttributeMaxDynamicSharedMemorySize, GEMM_SMEM);
    cudaFuncSetAttribute(k_mmagemm<0,0,0,1>, cudaFuncAttributeMaxDynamicSharedMemorySize, GEMM_SMEM);
    cudaFuncSetAttribute(k_mmagemm<1,1,1,0>, cudaFuncAttributeMaxDynamicSharedMemorySize, GEMM_SMEM);
    cudaFuncSetAttribute(k_mmagemm<2,1,0,1>, cudaFuncAttributeMaxDynamicSharedMemorySize, GEMM_SMEM);

    k_wtall<<<(C3*Cc + Cc*Cc + HIDN*Cc + Cc*HIDN + 255)/256, 256>>>(
        Wqkv, Wproj, W1, W2, wqkvT, wprojT, w1T, w2T);
    k_in<<<dim3(Ff/32, BT), 256>>>(x, xs, xn, n1g, n1b);
    k_mmagemm<1,0,0,0><<<dim3(C3/128, ROWS/256), 256, GEMM_SMEM>>>(xn, wqkvT, qkv, nullptr, nullptr, C3, Cc);
    k_attn<<<dim3(BT, Hh), 256, ATTN_SMEM>>>(qkv, dww, temp, att);
    k_mmagemm<0,0,0,1><<<dim3(Cc/128, ROWS/256), 256, GEMM_SMEM>>>(att, wprojT, out1, nullptr, xs, Cc, Cc);
    k_ln<<<ROWS, 256>>>(out1, xn, n2g, n2b);
    k_mmagemm<1,1,1,0><<<dim3(HIDN/128, ROWS/256), 256, GEMM_SMEM>>>(xn, w1T, hid, b1, nullptr, HIDN, Cc);
    k_mmagemm<2,1,0,1><<<dim3(Cc/128, ROWS/256), 256, GEMM_SMEM>>>(hid, w2T, d_out, b2, out1, Cc, HIDN);
}

// round 17
// speedup vs baseline: 1.1208x; 1.1208x over previous
#include <cuda_runtime.h>
#include <cuda_bf16.h>
#include <math.h>
#include <stdint.h>

#define Bb 4
#define Tt 64
#define Cc 256
#define Ff 256
#define Hh 8
#define Dd 32
#define HIDN 512
#define BT (Bb*Tt)            // 256
#define ROWS (BT*Ff)          // 65536
#define C3 (3*Cc)             // 768

// ---------------- scratch (device globals; resolved via cudaGetSymbolAddress) ----
__device__ float          g_xs  [ROWS*Cc];    // residual fp32 (raw transposed x)
__device__ float          g_out1[ROWS*Cc];    // after proj + residual
__device__ __nv_bfloat16  g_xn  [ROWS*Cc];    // LN out (bf16)
__device__ __nv_bfloat16  g_att [ROWS*Cc];    // attention out (bf16)
__device__ __nv_bfloat16  g_qkv [ROWS*C3];    // qkv bf16; reused as MLP hidden
__device__ __nv_bfloat16  g_wqkvT [C3*Cc];    // transposed bf16 weights [N][K]
__device__ __nv_bfloat16  g_wprojT[Cc*Cc];
__device__ __nv_bfloat16  g_w1T   [HIDN*Cc];
__device__ __nv_bfloat16  g_w2T   [Cc*HIDN];

__device__ __forceinline__ uint32_t smem_u32(const void* p) {
    uint32_t a;
    asm("{ .reg .u64 t; cvta.to.shared.u64 t, %1; cvt.u32.u64 %0, t; }" : "=r"(a) : "l"(p));
    return a;
}
__device__ __forceinline__ void ldsm4(uint32_t& r0, uint32_t& r1, uint32_t& r2, uint32_t& r3,
                                      uint32_t addr) {
    asm volatile("ldmatrix.sync.aligned.m8n8.x4.shared.b16 {%0,%1,%2,%3}, [%4];"
                 : "=r"(r0), "=r"(r1), "=r"(r2), "=r"(r3) : "r"(addr));
}
__device__ __forceinline__ void ldsm4t(uint32_t& r0, uint32_t& r1, uint32_t& r2, uint32_t& r3,
                                       uint32_t addr) {
    asm volatile("ldmatrix.sync.aligned.m8n8.x4.trans.shared.b16 {%0,%1,%2,%3}, [%4];"
                 : "=r"(r0), "=r"(r1), "=r"(r2), "=r"(r3) : "r"(addr));
}
__device__ __forceinline__ void mma16816(float* c, const uint32_t* a, const uint32_t* b) {
    asm volatile(
        "mma.sync.aligned.m16n8k16.row.col.f32.bf16.bf16.f32 "
        "{%0,%1,%2,%3}, {%4,%5,%6,%7}, {%8,%9}, {%0,%1,%2,%3};"
        : "+f"(c[0]), "+f"(c[1]), "+f"(c[2]), "+f"(c[3])
        : "r"(a[0]), "r"(a[1]), "r"(a[2]), "r"(a[3]), "r"(b[0]), "r"(b[1]));
}
__device__ __forceinline__ void cp16(uint32_t sdst, const void* gsrc) {
    asm volatile("cp.async.cg.shared.global [%0], [%1], 16;" :: "r"(sdst), "l"(gsrc));
}
__device__ __forceinline__ uint32_t ex2_bf16x2(uint32_t a) {
    uint32_t d;
    asm("ex2.approx.ftz.bf16x2 %0, %1;" : "=r"(d) : "r"(a));
    return d;
}
#define CP_COMMIT() asm volatile("cp.async.commit_group;" ::: "memory")
#define CP_WAIT(n)  asm volatile("cp.async.wait_group %0;" :: "n"(n) : "memory")

// ================= fused input: transpose x(b,c,t,f)->(bt,f,c) + LN1 =================
__global__ __launch_bounds__(256)
void k_in(const float* __restrict__ x, float* __restrict__ xs,
          __nv_bfloat16* __restrict__ xn,
          const float* __restrict__ g, const float* __restrict__ be) {
    __shared__ float tile[256][33];
    __shared__ float ps_[8][32], pq_[8][32];
    __shared__ float smu[32], srs[32];
    int bt = blockIdx.y, f0 = blockIdx.x * 32;
    int b = bt >> 6, t = bt & 63;
    int tid = threadIdx.x;
    int f = tid & 31, s = tid >> 5;

    const float* xb = x + ((size_t)b*Cc*Tt + t)*Ff + f0;
    float sm = 0.f, sq = 0.f;
    #pragma unroll 8
    for (int i = 0; i < 32; i++) {
        int c = s + i*8;
        float v = xb[(size_t)c*Tt*Ff + f];
        tile[c][f] = v;
        sm += v; sq += v*v;
    }
    ps_[s][f] = sm; pq_[s][f] = sq;
    __syncthreads();
    if (tid < 32) {
        float S = 0.f, Q = 0.f;
        #pragma unroll
        for (int k = 0; k < 8; k++) { S += ps_[k][tid]; Q += pq_[k][tid]; }
        float mu = S * (1.0f/Cc);
        float var = Q * (1.0f/Cc) - mu*mu;
        smu[tid] = mu;
        srs[tid] = rsqrtf(var + 1e-5f);
    }
    __syncthreads();
    float gc = g[tid], bc = be[tid];
    #pragma unroll 8
    for (int i = 0; i < 32; i++) {
        float v = tile[tid][i];
        size_t o = ((size_t)bt*Ff + f0 + i)*Cc + tid;
        xs[o] = v;
        xn[o] = __float2bfloat16((v - smu[i]) * srs[i] * gc + bc);
    }
}

// ================= layernorm (256) -> bf16 =================
__global__ void k_ln(const float* __restrict__ in, __nv_bfloat16* __restrict__ outn,
                     const float* __restrict__ g, const float* __restrict__ be) {
    int row = blockIdx.x;
    int tid = threadIdx.x;
    float v = in[(size_t)row*Cc + tid];
    float s = v, q = v*v;
    #pragma unroll
    for (int o = 16; o; o >>= 1) {
        s += __shfl_xor_sync(0xffffffffu, s, o);
        q += __shfl_xor_sync(0xffffffffu, q, o);
    }
    __shared__ float ws[8], wq[8], mv[2];
    int w = tid >> 5, l = tid & 31;
    if (l == 0) { ws[w] = s; wq[w] = q; }
    __syncthreads();
    if (tid == 0) {
        float S = 0.f, Q = 0.f;
        #pragma unroll
        for (int i = 0; i < 8; i++) { S += ws[i]; Q += wq[i]; }
        float mu = S * (1.0f/Cc);
        float var = Q * (1.0f/Cc) - mu*mu;
        mv[0] = mu;
        mv[1] = rsqrtf(var + 1e-5f);
    }
    __syncthreads();
    outn[(size_t)row*Cc + tid] = __float2bfloat16((v - mv[0]) * mv[1] * g[tid] + be[tid]);
}

// ================= all weight transposes in one kernel =================
__global__ void k_wtall(const float* __restrict__ Wqkv, const float* __restrict__ Wproj,
                        const float* __restrict__ W1, const float* __restrict__ W2,
                        __nv_bfloat16* __restrict__ wqkvT, __nv_bfloat16* __restrict__ wprojT,
                        __nv_bfloat16* __restrict__ w1T, __nv_bfloat16* __restrict__ w2T) {
    int idx = blockIdx.x * 256 + threadIdx.x;
    if (idx < C3*Cc) {
        int n = idx / Cc, k = idx - n*Cc;
        wqkvT[idx] = __float2bfloat16(Wqkv[(size_t)k*C3 + n]);
    } else if (idx < C3*Cc + Cc*Cc) {
        int j = idx - C3*Cc;
        int n = j / Cc, k = j - n*Cc;
        wprojT[j] = __float2bfloat16(Wproj[(size_t)k*Cc + n]);
    } else if (idx < C3*Cc + Cc*Cc + HIDN*Cc) {
        int j = idx - C3*Cc - Cc*Cc;
        int n = j / Cc, k = j - n*Cc;
        w1T[j] = __float2bfloat16(W1[(size_t)k*HIDN + n]);
    } else if (idx < C3*Cc + Cc*Cc + HIDN*Cc + Cc*HIDN) {
        int j = idx - C3*Cc - Cc*Cc - HIDN*Cc;
        int n = j / HIDN, k = j - n*HIDN;
        w2T[j] = __float2bfloat16(W2[(size_t)k*Cc + n]);
    }
}

// ================= HMMA bf16 GEMM: C = A(M,K) @ Bt(N,K)^T =================
// CTA 128x128, 8 warps 2Mx4N, K chunks of 64, 3-stage cp.async ring,
// ONE __syncthreads per chunk (bottom barrier proven redundant: the top sync
// of iteration c orders compute(c-1) before load(c+2) which reuses its stage).
#define GEMM_SMEM (6*128*64*2)   // 98304 B
template<int OUT_MODE, int HAS_BIAS, int GELU_F, int HAS_RES>
__global__ __launch_bounds__(256, 2)
void k_mmagemm(const __nv_bfloat16* __restrict__ A, const __nv_bfloat16* __restrict__ Bt,
               void* __restrict__ Co, const float* __restrict__ bias,
               const float* __restrict__ res, int N, int K) {
    extern __shared__ __nv_bfloat16 smg[];
    int tid = threadIdx.x, wid = tid >> 5, lid = tid & 31;
    int m0 = blockIdx.y * 128, n0 = blockIdx.x * 128;
    int wm = (wid & 1) * 64;
    int wn = (wid >> 1) * 32;

    int lrow = tid >> 3, lkb = tid & 7;
    uint32_t swoff = (lkb ^ (lrow & 7)) * 8;

    float c[4][4][4];
    #pragma unroll
    for (int mi = 0; mi < 4; mi++)
        #pragma unroll
        for (int ni = 0; ni < 4; ni++)
            #pragma unroll
            for (int j = 0; j < 4; j++) c[mi][ni][j] = 0.f;

    uint32_t sA0 = smem_u32(smg);
    uint32_t sB0 = sA0 + 3*16384;
    int nch = K >> 6;

    auto load_chunk = [&](int ck) {
        int k0 = ck << 6;
        uint32_t ab = sA0 + (ck % 3) * 16384;
        uint32_t bb = sB0 + (ck % 3) * 16384;
        const __nv_bfloat16* ga = A  + (size_t)(m0 + lrow)*K + k0 + lkb*8;
        const __nv_bfloat16* gb = Bt + (size_t)(n0 + lrow)*K + k0 + lkb*8;
        #pragma unroll
        for (int i = 0; i < 4; i++) {
            uint32_t d = ((lrow + i*32)*64 + swoff) * 2;
            cp16(ab + d, ga + (size_t)(i*32)*K);
            cp16(bb + d, gb + (size_t)(i*32)*K);
        }
        CP_COMMIT();
    };

    load_chunk(0);
    if (nch > 1) load_chunk(1);

    for (int cck = 0; cck < nch; cck++) {
        if (cck + 1 < nch) { CP_WAIT(1); } else { CP_WAIT(0); }
        __syncthreads();
        if (cck + 2 < nch) load_chunk(cck + 2);

        uint32_t sA = sA0 + (cck % 3) * 16384;
        uint32_t sB = sB0 + (cck % 3) * 16384;
        #pragma unroll
        for (int ks = 0; ks < 4; ks++) {
            uint32_t a[4][4], b[4][2];
            #pragma unroll
            for (int mi = 0; mi < 4; mi++) {
                int row = wm + mi*16 + (lid & 15);
                int kb  = ks*2 + (lid >> 4);
                uint32_t ad = sA + (row*64 + ((kb ^ (row & 7))*8))*2;
                ldsm4(a[mi][0], a[mi][1], a[mi][2], a[mi][3], ad);
            }
            #pragma unroll
            for (int nh = 0; nh < 2; nh++) {
                int nrow = wn + nh*16 + (lid & 7) + ((lid >> 4) << 3);
                int kb   = ks*2 + ((lid >> 3) & 1);
                uint32_t bd = sB + (nrow*64 + ((kb ^ (nrow & 7))*8))*2;
                uint32_t r0, r1, r2, r3;
                ldsm4(r0, r1, r2, r3, bd);
                b[nh*2+0][0] = r0; b[nh*2+0][1] = r1;
                b[nh*2+1][0] = r2; b[nh*2+1][1] = r3;
            }
            #pragma unroll
            for (int mi = 0; mi < 4; mi++)
                #pragma unroll
                for (int ni = 0; ni < 4; ni++)
                    mma16816(c[mi][ni], a[mi], b[ni]);
        }
    }

    int qr = lid >> 2, qc = (lid & 3) * 2;
    #pragma unroll
    for (int mi = 0; mi < 4; mi++) {
        #pragma unroll
        for (int half = 0; half < 2; half++) {
            int m = m0 + wm + mi*16 + qr + half*8;
            #pragma unroll
            for (int ni = 0; ni < 4; ni++) {
                int n = n0 + wn + ni*8 + qc;
                float v0 = c[mi][ni][half*2+0];
                float v1 = c[mi][ni][half*2+1];
                if (HAS_BIAS) { v0 += bias[n]; v1 += bias[n+1]; }
                if (GELU_F) {
                    v0 = 0.5f*v0*(1.0f + erff(v0*0.7071067811865475f));
                    v1 = 0.5f*v1*(1.0f + erff(v1*0.7071067811865475f));
                }
                if (HAS_RES) {
                    float2 r2 = *(const float2*)&res[(size_t)m*N + n];
                    v0 += r2.x; v1 += r2.y;
                }
                if (OUT_MODE == 1) {
                    *(__nv_bfloat162*)((__nv_bfloat16*)Co + (size_t)m*N + n) =
                        __floats2bfloat162_rn(v0, v1);
                } else if (OUT_MODE == 0) {
                    *(float2*)((float*)Co + (size_t)m*N + n) = make_float2(v0, v1);
                } else {
                    int bt2 = m >> 8, fF = m & 255;
                    int b2 = bt2 >> 6, t2 = bt2 & 63;
                    float* op = (float*)Co + ((size_t)(b2*Cc + n)*Tt + t2)*Ff + fF;
                    op[0] = v0;
                    op[(size_t)Tt*Ff] = v1;
                }
            }
        }
    }
}

// ================= attention via HMMA (conv3 fused), block per (bt,h) =================
// (round-15 state, frozen)
#define ATTN_SMEM (3*256*40*2)   // 61440 B

__global__ __launch_bounds__(256, 2)
void k_attn(const __nv_bfloat16* __restrict__ qkvg, const float* __restrict__ dww,
            const float* __restrict__ temp, __nv_bfloat16* __restrict__ attn_out) {
    extern __shared__ __nv_bfloat16 smA[];
    __nv_bfloat16* Qs = smA;
    __nv_bfloat16* Ks = smA + 256*40;
    __nv_bfloat16* Vs = smA + 2*256*40;
    __shared__ float wsm[3*32*3];

    int bt = blockIdx.x, h = blockIdx.y;
    int tid = threadIdx.x, w = tid >> 5, l = tid & 31;
    const __nv_bfloat16* qkvb = qkvg + (size_t)bt*Ff*C3;
    float tpl = temp[h] * 1.44269504f;

    if (tid < 96) {
        int t = tid >> 5, d = tid & 31;
        int ch = t*Cc + h*Dd + d;
        wsm[tid*3+0] = dww[ch*3+0];
        wsm[tid*3+1] = dww[ch*3+1];
        wsm[tid*3+2] = dww[ch*3+2];
    }
    __syncthreads();

    {
        int j = tid;
        bool hasm = (j > 0), hasp = (j < Ff-1);
        const __nv_bfloat16* base = qkvb + (size_t)j*C3 + h*Dd;
        float acc[32];
        const uint4 z4 = make_uint4(0u, 0u, 0u, 0u);

        auto conv_one = [&](int off, const float* wt) {
            uint4 rm[4], rc[4], rp[4];
            const uint4* pc = (const uint4*)(base + off);
            const uint4* pm = (const uint4*)(base + off - C3);
            const uint4* pp = (const uint4*)(base + off + C3);
            #pragma unroll
            for (int i = 0; i < 4; i++) {
                rc[i] = pc[i];
                rm[i] = hasm ? pm[i] : z4;
                rp[i] = hasp ? pp[i] : z4;
            }
            const __nv_bfloat162* m2 = (const __nv_bfloat162*)rm;
            const __nv_bfloat162* c2 = (const __nv_bfloat162*)rc;
            const __nv_bfloat162* p2 = (const __nv_bfloat162*)rp;
            #pragma unroll
            for (int d = 0; d < 16; d++) {
                float2 cv = __bfloat1622float2(c2[d]);
                float2 mv = __bfloat1622float2(m2[d]);
                float2 pv = __bfloat1622float2(p2[d]);
                acc[2*d]   = wt[(2*d)*3+0]*mv.x + wt[(2*d)*3+1]*cv.x + wt[(2*d)*3+2]*pv.x;
                acc[2*d+1] = wt[(2*d+1)*3+0]*mv.y + wt[(2*d+1)*3+1]*cv.y + wt[(2*d+1)*3+2]*pv.y;
            }
        };
        auto store_s = [&](__nv_bfloat16* T, float sc) {
            uint4 pk4[4];
            uint32_t* pk = (uint32_t*)pk4;
            #pragma unroll
            for (int d = 0; d < 16; d++) {
                __nv_bfloat162 hh = __floats2bfloat162_rn(acc[2*d]*sc, acc[2*d+1]*sc);
                pk[d] = *(uint32_t*)&hh;
            }
            uint4* dst = (uint4*)(T + (size_t)j*40);
            #pragma unroll
            for (int i = 0; i < 4; i++) dst[i] = pk4[i];
        };

        conv_one(0, wsm);
        float ss = 0.f;
        #pragma unroll
        for (int d = 0; d < 32; d++) ss += acc[d]*acc[d];
        store_s(Qs, 1.f / fmaxf(sqrtf(ss), 1e-12f));

        conv_one(Cc, wsm + 96);
        ss = 0.f;
        #pragma unroll
        for (int d = 0; d < 32; d++) ss += acc[d]*acc[d];
        store_s(Ks, 1.f / fmaxf(sqrtf(ss), 1e-12f));

        conv_one(2*Cc, wsm + 192);
        store_s(Vs, 1.f);
    }
    __syncthreads();

    uint32_t sQ = smem_u32(Qs), sK = smem_u32(Ks), sV = smem_u32(Vs);
    int lid = l;
    int qr = lid >> 2;
    int m0a = w*32, m0b = w*32 + 16;

    uint32_t aA[2][4], aB[2][4];
    #pragma unroll
    for (int ks = 0; ks < 2; ks++) {
        int kb = ks*2 + (lid >> 4);
        ldsm4(aA[ks][0], aA[ks][1], aA[ks][2], aA[ks][3],
              sQ + ((m0a + (lid & 15))*40 + kb*8)*2);
        ldsm4(aB[ks][0], aB[ks][1], aB[ks][2], aB[ks][3],
              sQ + ((m0b + (lid & 15))*40 + kb*8)*2);
    }

    float ovA[4][4], ovB[4][4];
    #pragma unroll
    for (int nt = 0; nt < 4; nt++)
        #pragma unroll
        for (int j = 0; j < 4; j++) { ovA[nt][j] = 0.f; ovB[nt][j] = 0.f; }
    float zAlo = 0.f, zAhi = 0.f, zBlo = 0.f, zBhi = 0.f;

    for (int ch = 0; ch < 8; ch++) {
        float sA_[4][4], sB_[4][4];
        #pragma unroll
        for (int nt = 0; nt < 4; nt++)
            #pragma unroll
            for (int j = 0; j < 4; j++) { sA_[nt][j] = 0.f; sB_[nt][j] = 0.f; }
        #pragma unroll
        for (int g = 0; g < 2; g++) {
            #pragma unroll
            for (int ks = 0; ks < 2; ks++) {
                int nrow = ch*32 + g*16 + (lid & 7) + ((lid >> 4) << 3);
                int kb   = ks*2 + ((lid >> 3) & 1);
                uint32_t r0, r1, r2, r3;
                ldsm4(r0, r1, r2, r3, sK + (nrow*40 + kb*8)*2);
                uint32_t b0[2] = {r0, r1}, b1[2] = {r2, r3};
                mma16816(sA_[g*2],   aA[ks], b0);
                mma16816(sA_[g*2+1], aA[ks], b1);
                mma16816(sB_[g*2],   aB[ks], b0);
                mma16816(sB_[g*2+1], aB[ks], b1);
            }
        }
        #pragma unroll
        for (int kk = 0; kk < 2; kk++) {
            uint32_t paA[4], paB[4];
            {
                __nv_bfloat162 t0 = __floats2bfloat162_rn(sA_[2*kk][0]*tpl,   sA_[2*kk][1]*tpl);
                __nv_bfloat162 t1 = __floats2bfloat162_rn(sA_[2*kk][2]*tpl,   sA_[2*kk][3]*tpl);
                __nv_bfloat162 t2 = __floats2bfloat162_rn(sA_[2*kk+1][0]*tpl, sA_[2*kk+1][1]*tpl);
                __nv_bfloat162 t3 = __floats2bfloat162_rn(sA_[2*kk+1][2]*tpl, sA_[2*kk+1][3]*tpl);
                paA[0] = ex2_bf16x2(*(uint32_t*)&t0);
                paA[1] = ex2_bf16x2(*(uint32_t*)&t1);
                paA[2] = ex2_bf16x2(*(uint32_t*)&t2);
                paA[3] = ex2_bf16x2(*(uint32_t*)&t3);
                __nv_bfloat162 u0 = __floats2bfloat162_rn(sB_[2*kk][0]*tpl,   sB_[2*kk][1]*tpl);
                __nv_bfloat162 u1 = __floats2bfloat162_rn(sB_[2*kk][2]*tpl,   sB_[2*kk][3]*tpl);
                __nv_bfloat162 u2 = __floats2bfloat162_rn(sB_[2*kk+1][0]*tpl, sB_[2*kk+1][1]*tpl);
                __nv_bfloat162 u3 = __floats2bfloat162_rn(sB_[2*kk+1][2]*tpl, sB_[2*kk+1][3]*tpl);
                paB[0] = ex2_bf16x2(*(uint32_t*)&u0);
                paB[1] = ex2_bf16x2(*(uint32_t*)&u1);
                paB[2] = ex2_bf16x2(*(uint32_t*)&u2);
                paB[3] = ex2_bf16x2(*(uint32_t*)&u3);
            }
            {
                float2 p0 = __bfloat1622float2(*(__nv_bfloat162*)&paA[0]);
                float2 p1 = __bfloat1622float2(*(__nv_bfloat162*)&paA[1]);
                float2 p2 = __bfloat1622float2(*(__nv_bfloat162*)&paA[2]);
                float2 p3 = __bfloat1622float2(*(__nv_bfloat162*)&paA[3]);
                zAlo += p0.x + p0.y + p2.x + p2.y;
                zAhi += p1.x + p1.y + p3.x + p3.y;
                float2 q0 = __bfloat1622float2(*(__nv_bfloat162*)&paB[0]);
                float2 q1 = __bfloat1622float2(*(__nv_bfloat162*)&paB[1]);
                float2 q2 = __bfloat1622float2(*(__nv_bfloat162*)&paB[2]);
                float2 q3 = __bfloat1622float2(*(__nv_bfloat162*)&paB[3]);
                zBlo += q0.x + q0.y + q2.x + q2.y;
                zBhi += q1.x + q1.y + q3.x + q3.y;
            }
            int vrow = ch*32 + kk*16 + (lid & 15);
            #pragma unroll
            for (int half = 0; half < 2; half++) {
                uint32_t r0, r1, r2, r3;
                ldsm4t(r0, r1, r2, r3, sV + (vrow*40)*2 + (lid >> 4)*16 + half*32);
                uint32_t b0[2] = {r0, r1}, b1[2] = {r2, r3};
                mma16816(ovA[half*2+0], paA, b0);
                mma16816(ovA[half*2+1], paA, b1);
                mma16816(ovB[half*2+0], paB, b0);
                mma16816(ovB[half*2+1], paB, b1);
            }
        }
    }

    #pragma unroll
    for (int o = 1; o <= 2; o <<= 1) {
        zAlo += __shfl_xor_sync(0xffffffffu, zAlo, o);
        zAhi += __shfl_xor_sync(0xffffffffu, zAhi, o);
        zBlo += __shfl_xor_sync(0xffffffffu, zBlo, o);
        zBhi += __shfl_xor_sync(0xffffffffu, zBhi, o);
    }
    float iAlo = 1.f/zAlo, iAhi = 1.f/zAhi;
    float iBlo = 1.f/zBlo, iBhi = 1.f/zBhi;
    #pragma unroll
    for (int nt = 0; nt < 4; nt++) {
        int col = h*Dd + nt*8 + (lid & 3)*2;
        *(__nv_bfloat162*)&attn_out[((size_t)bt*Ff + m0a + qr    )*Cc + col] =
            __floats2bfloat162_rn(ovA[nt][0]*iAlo, ovA[nt][1]*iAlo);
        *(__nv_bfloat162*)&attn_out[((size_t)bt*Ff + m0a + qr + 8)*Cc + col] =
            __floats2bfloat162_rn(ovA[nt][2]*iAhi, ovA[nt][3]*iAhi);
        *(__nv_bfloat162*)&attn_out[((size_t)bt*Ff + m0b + qr    )*Cc + col] =
            __floats2bfloat162_rn(ovB[nt][0]*iBlo, ovB[nt][1]*iBlo);
        *(__nv_bfloat162*)&attn_out[((size_t)bt*Ff + m0b + qr + 8)*Cc + col] =
            __floats2bfloat162_rn(ovB[nt][2]*iBhi, ovB[nt][3]*iBhi);
    }
}

// ================= launch =================
extern "C" void kernel_launch(void* const* d_in, const int* in_sizes, int n_in,
                              void* d_out, int out_size) {
    const float *x, *n1g, *n1b, *Wqkv, *dww, *Wproj, *temp, *n2g, *n2b, *W1, *b1, *W2, *b2;
    const int X_SIZE = Bb*Cc*Tt*Ff;
    if (n_in >= 13 && in_sizes[0] == X_SIZE) {
        x     = (const float*)d_in[0];  n1g   = (const float*)d_in[1];
        n1b   = (const float*)d_in[2];  Wqkv  = (const float*)d_in[3];
        dww   = (const float*)d_in[4];  Wproj = (const float*)d_in[5];
        temp  = (const float*)d_in[6];  n2g   = (const float*)d_in[7];
        n2b   = (const float*)d_in[8];  W1    = (const float*)d_in[9];
        b1    = (const float*)d_in[10]; W2    = (const float*)d_in[11];
        b2    = (const float*)d_in[12];
    } else {
        W1    = (const float*)d_in[0];  W2    = (const float*)d_in[1];
        Wproj = (const float*)d_in[2];  Wqkv  = (const float*)d_in[3];
        b1    = (const float*)d_in[4];  b2    = (const float*)d_in[5];
        dww   = (const float*)d_in[6];  n1b   = (const float*)d_in[7];
        n1g   = (const float*)d_in[8];  n2b   = (const float*)d_in[9];
        n2g   = (const float*)d_in[10]; temp  = (const float*)d_in[11];
        x     = (const float*)d_in[12];
    }

    void *vp;
    float *xs, *out1;
    __nv_bfloat16 *xn, *att, *qkv, *wqkvT, *wprojT, *w1T, *w2T;
    cudaGetSymbolAddress(&vp, g_xs);     xs     = (float*)vp;
    cudaGetSymbolAddress(&vp, g_out1);   out1   = (float*)vp;
    cudaGetSymbolAddress(&vp, g_xn);     xn     = (__nv_bfloat16*)vp;
    cudaGetSymbolAddress(&vp, g_att);    att    = (__nv_bfloat16*)vp;
    cudaGetSymbolAddress(&vp, g_qkv);    qkv    = (__nv_bfloat16*)vp;
    cudaGetSymbolAddress(&vp, g_wqkvT);  wqkvT  = (__nv_bfloat16*)vp;
    cudaGetSymbolAddress(&vp, g_wprojT); wprojT = (__nv_bfloat16*)vp;
    cudaGetSymbolAddress(&vp, g_w1T);    w1T    = (__nv_bfloat16*)vp;
    cudaGetSymbolAddress(&vp, g_w2T);    w2T    = (__nv_bfloat16*)vp;
    __nv_bfloat16* hid = qkv;

    cudaFuncSetAttribute(k_attn, cudaFuncAttributeMaxDynamicSharedMemorySize, ATTN_SMEM);
    cudaFuncSetAttribute(k_mmagemm<1,0,0,0>, cudaFuncAttributeMaxDynamicSharedMemorySize, GEMM_SMEM);
    cudaFuncSetAttribute(k_mmagemm<0,0,0,1>, cudaFuncAttributeMaxDynamicSharedMemorySize, GEMM_SMEM);
    cudaFuncSetAttribute(k_mmagemm<1,1,1,0>, cudaFuncAttributeMaxDynamicSharedMemorySize, GEMM_SMEM);
    cudaFuncSetAttribute(k_mmagemm<2,1,0,1>, cudaFuncAttributeMaxDynamicSharedMemorySize, GEMM_SMEM);

    k_wtall<<<(C3*Cc + Cc*Cc + HIDN*Cc + Cc*HIDN + 255)/256, 256>>>(
        Wqkv, Wproj, W1, W2, wqkvT, wprojT, w1T, w2T);
    k_in<<<dim3(Ff/32, BT), 256>>>(x, xs, xn, n1g, n1b);
    k_mmagemm<1,0,0,0><<<dim3(C3/128, ROWS/128), 256, GEMM_SMEM>>>(xn, wqkvT, qkv, nullptr, nullptr, C3, Cc);
    k_attn<<<dim3(BT, Hh), 256, ATTN_SMEM>>>(qkv, dww, temp, att);
    k_mmagemm<0,0,0,1><<<dim3(Cc/128, ROWS/128), 256, GEMM_SMEM>>>(att, wprojT, out1, nullptr, xs, Cc, Cc);
    k_ln<<<ROWS, 256>>>(out1, xn, n2g, n2b);
    k_mmagemm<1,1,1,0><<<dim3(HIDN/128, ROWS/128), 256, GEMM_SMEM>>>(xn, w1T, hid, b1, nullptr, HIDN, Cc);
    k_mmagemm<2,1,0,1><<<dim3(Cc/128, ROWS/128), 256, GEMM_SMEM>>>(hid, w2T, d_out, b2, out1, Cc, HIDN);
}